// round 3
// baseline (speedup 1.0000x reference)
#include <cuda_runtime.h>
#include <cstdint>

#define VNUM    100000
#define KNZ     8
#define BASE    64
#define DIM     9
#define BATCH   16
#define TV      128              // vertices per block
#define THREADS 256
#define SLAB    (BASE * DIM)     // 576 rows of [16 batches]
#define RSTRIDE 20               // row stride in floats (80B): 5r mod 8 covers all quads
#define NELEM   (TV * DIM)       // 1152 elements per block

#define SMEM_FS_FLOATS (SLAB * RSTRIDE)                  // 11520 floats = 46080 B
#define SMEM_TOTAL_B   (SMEM_FS_FLOATS * 4 + TV * KNZ * 8) // + woff float2 = 54272 B

// Flag: 1 if vb_index is int64 on device, 0 if int32.
__device__ int g_vb_is64;

// int64 values in [0,64) have zero odd int32 slots; int32 data has random odd slots.
__global__ void detect_vb_dtype_kernel(const int* __restrict__ vb32) {
    __shared__ int any_nonzero;
    if (threadIdx.x == 0) any_nonzero = 0;
    __syncthreads();
    for (int i = threadIdx.x; i < 4096; i += blockDim.x)
        if (vb32[2 * i + 1] != 0) any_nonzero = 1;
    __syncthreads();
    if (threadIdx.x == 0) g_vb_is64 = (any_nonzero ? 0 : 1);
}

__global__ __launch_bounds__(THREADS, 4)
void skin_kernel(const float* __restrict__ base_fs,
                 const float* __restrict__ ws,
                 const void*  __restrict__ vb_raw,
                 float* __restrict__ out) {
    extern __shared__ float smem[];
    float*  fs_s   = smem;                               // [576 rows][20], batch 0..15 in [0..16)
    float2* woff_s = (float2*)(smem + SMEM_FS_FLOATS);   // [TV][8] {w, bitcast(row_off)}

    const int tid = threadIdx.x;
    const int v0  = blockIdx.x * TV;

    // ---- Phase 1a: stage base_fs transposed: fs_s[r*20 + b] = base_fs[b*576 + r] ----
    // Coalesced gmem reads; smem writes are 4-way conflicted (acceptable, once/block).
    #pragma unroll
    for (int k = 0; k < (BATCH * SLAB) / THREADS; k++) {
        const int i = tid + k * THREADS;
        const int b = i / SLAB;
        const int r = i - b * SLAB;
        fs_s[r * RSTRIDE + b] = base_fs[i];
    }

    // ---- Phase 1b: per-vertex softmax weights + packed gather row offsets ----
    const int is64 = g_vb_is64;
    for (int t = tid; t < TV; t += THREADS) {
        const int v = v0 + t;
        if (v < VNUM) {
            const float4* wp = reinterpret_cast<const float4*>(ws + (size_t)v * KNZ);
            float4 a = wp[0], b4 = wp[1];
            float x[8] = {a.x, a.y, a.z, a.w, b4.x, b4.y, b4.z, b4.w};
            float m = x[0];
            #pragma unroll
            for (int j = 1; j < 8; j++) m = fmaxf(m, x[j]);
            float s = 0.f;
            #pragma unroll
            for (int j = 0; j < 8; j++) { x[j] = __expf(x[j] - m); s += x[j]; }
            const float inv = 1.f / s;

            int idx[8];
            if (is64) {
                const longlong2* ip =
                    reinterpret_cast<const longlong2*>((const char*)vb_raw + (size_t)v * KNZ * 8);
                #pragma unroll
                for (int j = 0; j < 4; j++) {
                    longlong2 ii = ip[j];
                    idx[2 * j]     = (int)ii.x;
                    idx[2 * j + 1] = (int)ii.y;
                }
            } else {
                const int4* ip =
                    reinterpret_cast<const int4*>((const char*)vb_raw + (size_t)v * KNZ * 4);
                int4 i0 = ip[0], i1 = ip[1];
                idx[0] = i0.x; idx[1] = i0.y; idx[2] = i0.z; idx[3] = i0.w;
                idx[4] = i1.x; idx[5] = i1.y; idx[6] = i1.z; idx[7] = i1.w;
            }
            #pragma unroll
            for (int j = 0; j < 8; j++)
                woff_s[t * KNZ + j] =
                    make_float2(x[j] * inv, __int_as_float(idx[j] * (DIM * RSTRIDE)));
        }
    }
    __syncthreads();

    // ---- Phase 2: lane owns element e = tl*9+d (consecutive across warp), all 16 batches ----
    // Per base: each lane reads 4 quads of its 80B-strided row; consecutive rows start at
    // bank-quad 5r mod 8 (a permutation) -> every 128B wavefront fully used (4 cyc / 512B).
    for (int e = tid; e < NELEM; e += THREADS) {
        const int tl = e / DIM;
        const int d  = e - tl * DIM;
        const int v  = v0 + tl;
        if (v >= VNUM) continue;

        float w[8];
        int   p[8];
        const int drow = d * RSTRIDE;
        #pragma unroll
        for (int j = 0; j < 8; j++) {
            float2 wo = woff_s[tl * KNZ + j];
            w[j] = wo.x;
            p[j] = __float_as_int(wo.y) + drow;
        }

        float acc[BATCH];
        #pragma unroll
        for (int b = 0; b < BATCH; b++) acc[b] = 0.f;

        #pragma unroll
        for (int j = 0; j < 8; j++) {
            const float4* f = reinterpret_cast<const float4*>(fs_s + p[j]);
            const float wj = w[j];
            float4 q0 = f[0], q1 = f[1], q2 = f[2], q3 = f[3];
            acc[0]  += wj * q0.x; acc[1]  += wj * q0.y;
            acc[2]  += wj * q0.z; acc[3]  += wj * q0.w;
            acc[4]  += wj * q1.x; acc[5]  += wj * q1.y;
            acc[6]  += wj * q1.z; acc[7]  += wj * q1.w;
            acc[8]  += wj * q2.x; acc[9]  += wj * q2.y;
            acc[10] += wj * q2.z; acc[11] += wj * q2.w;
            acc[12] += wj * q3.x; acc[13] += wj * q3.y;
            acc[14] += wj * q3.z; acc[15] += wj * q3.w;
        }

        // Coalesced: 32 consecutive e per warp -> 128B per batch-plane store.
        const size_t obase = (size_t)v0 * DIM + e;
        #pragma unroll
        for (int b = 0; b < BATCH; b++)
            out[(size_t)b * ((size_t)VNUM * DIM) + obase] = acc[b];
    }
}

extern "C" void kernel_launch(void* const* d_in, const int* in_sizes, int n_in,
                              void* d_out, int out_size) {
    const float* base_fs = (const float*)d_in[0];   // [16, 576] f32
    const float* ws      = (const float*)d_in[1];   // [800000] f32
    const void*  vb      = d_in[2];                 // [800000] i64 or i32 (detected)
    // d_in[3] = vv_index: statically repeat(arange(VNUM), 8); unused.
    float* out = (float*)d_out;                     // [16, 100000, 9] f32

    static bool attr_set = false;
    if (!attr_set) {
        cudaFuncSetAttribute(skin_kernel,
                             cudaFuncAttributeMaxDynamicSharedMemorySize, SMEM_TOTAL_B);
        attr_set = true;
    }

    detect_vb_dtype_kernel<<<1, 256>>>((const int*)vb);
    const int blocks = (VNUM + TV - 1) / TV;        // 782
    skin_kernel<<<blocks, THREADS, SMEM_TOTAL_B>>>(base_fs, ws, vb, out);
}

// round 5
// speedup vs baseline: 1.5083x; 1.5083x over previous
#include <cuda_runtime.h>
#include <cuda_fp16.h>
#include <cstdint>

#define VNUM   100000
#define KNZ    8
#define BASE   64
#define DIM    9
#define BATCH  16
#define TV     128
#define THREADS 256
#define NCOL   (BATCH * DIM)     // 144
#define NELEM  (TV * DIM)        // 1152
#define SLAB   (BASE * DIM)      // 576

#define ASTR   72                // A row stride in halves (144 B)
#define BSTR   72                // B row stride in halves (144 B)
#define OFF_A  0                 // A fp16 [128][72]  = 18432 B
#define OFF_B  (TV * ASTR * 2)   // B fp16 [144][72]  = 20736 B  (ends 39168)
#define OFF_STAGE 0              // stage f32 [16][1152] = 73728 B (aliases A+B)
#define SMEM_TOTAL (BATCH * NELEM * 4)   // 73728 B

__device__ int g_vb_is64;

// int64 values in [0,64) have zero odd int32 slots; int32 data has random odd slots.
__global__ void detect_vb_dtype_kernel(const int* __restrict__ vb32) {
    __shared__ int any_nonzero;
    if (threadIdx.x == 0) any_nonzero = 0;
    __syncthreads();
    for (int i = threadIdx.x; i < 4096; i += blockDim.x)
        if (vb32[2 * i + 1] != 0) any_nonzero = 1;
    __syncthreads();
    if (threadIdx.x == 0) g_vb_is64 = (any_nonzero ? 0 : 1);
}

static __device__ __forceinline__ void mma16816(float c[4],
                                                const uint32_t a[4],
                                                uint32_t b0, uint32_t b1) {
    asm volatile(
        "mma.sync.aligned.m16n8k16.row.col.f32.f16.f16.f32 "
        "{%0,%1,%2,%3}, {%4,%5,%6,%7}, {%8,%9}, {%0,%1,%2,%3};"
        : "+f"(c[0]), "+f"(c[1]), "+f"(c[2]), "+f"(c[3])
        : "r"(a[0]), "r"(a[1]), "r"(a[2]), "r"(a[3]), "r"(b0), "r"(b1));
}

__global__ __launch_bounds__(THREADS)
void skin_mma_kernel(const float* __restrict__ base_fs,
                     const float* __restrict__ ws,
                     const void*  __restrict__ vb_raw,
                     float* __restrict__ out) {
    extern __shared__ char smem[];
    const int tid = threadIdx.x;
    const int wid = tid >> 5;
    const int lid = tid & 31;
    const int g   = lid >> 2;      // mma group id (0..7)
    const int tg  = lid & 3;       // thread-in-group (0..3)
    const int v0  = blockIdx.x * TV;

    // ---- Phase 1: zero A ----
    uint32_t* A32 = (uint32_t*)(smem + OFF_A);
    #pragma unroll
    for (int it = 0; it < (TV * ASTR * 2 / 4) / THREADS; it++)      // 18
        A32[tid + it * THREADS] = 0u;

    // ---- Phase 2: build B = FS^T fp16, n-major [144 rows][72 halves] ----
    // B[n=b*9+d][k] = base_fs[b*576 + k*9 + d]; gmem reads coalesced.
    __half* Bh = (__half*)(smem + OFF_B);
    #pragma unroll
    for (int it = 0; it < (BATCH * SLAB) / THREADS; it++) {          // 36
        const int i = tid + it * THREADS;
        const int b = i / SLAB;
        const int r = i - b * SLAB;
        const int k = r / DIM;
        const int d = r - k * DIM;
        Bh[(b * DIM + d) * BSTR + k] = __float2half_rn(base_fs[i]);
    }

    // ---- Phase 3: softmax + scatter A[vloc][base] (duplicates merged) ----
    const int is64 = g_vb_is64;
    if (tid < TV) {
        const int v = v0 + tid;
        if (v < VNUM) {
            const float4* wp = reinterpret_cast<const float4*>(ws + (size_t)v * KNZ);
            float4 a4 = wp[0], b4 = wp[1];
            float x[8] = {a4.x, a4.y, a4.z, a4.w, b4.x, b4.y, b4.z, b4.w};
            float m = x[0];
            #pragma unroll
            for (int j = 1; j < 8; j++) m = fmaxf(m, x[j]);
            float s = 0.f;
            #pragma unroll
            for (int j = 0; j < 8; j++) { x[j] = __expf(x[j] - m); s += x[j]; }
            const float inv = 1.f / s;

            int idx[8];
            if (is64) {
                const longlong2* ip =
                    reinterpret_cast<const longlong2*>((const char*)vb_raw + (size_t)v * KNZ * 8);
                #pragma unroll
                for (int j = 0; j < 4; j++) {
                    longlong2 ii = ip[j];
                    idx[2 * j] = (int)ii.x; idx[2 * j + 1] = (int)ii.y;
                }
            } else {
                const int4* ip =
                    reinterpret_cast<const int4*>((const char*)vb_raw + (size_t)v * KNZ * 4);
                int4 i0 = ip[0], i1 = ip[1];
                idx[0] = i0.x; idx[1] = i0.y; idx[2] = i0.z; idx[3] = i0.w;
                idx[4] = i1.x; idx[5] = i1.y; idx[6] = i1.z; idx[7] = i1.w;
            }
            __half* Ah = (__half*)(smem + OFF_A) + tid * ASTR;
            #pragma unroll
            for (int j = 0; j < 8; j++) {
                bool first = true;
                #pragma unroll
                for (int i = 0; i < 8; i++)
                    if (i < j && idx[i] == idx[j]) first = false;
                if (first) {
                    float acc = 0.f;
                    #pragma unroll
                    for (int i = 0; i < 8; i++)
                        if (i >= j && idx[i] == idx[j]) acc += x[i];
                    Ah[idx[j]] = __float2half_rn(acc * inv);
                }
            }
        }
    }
    __syncthreads();

    // ---- Phase 4: warp w computes D rows [16w,16w+16) x 144 cols ----
    // A frags cached for all 4 k-steps (conflict-free: row stride 144B).
    uint32_t afr[4][4];
    {
        const char* Abase = smem + OFF_A + (wid * 16 + g) * (ASTR * 2) + 4 * tg;
        #pragma unroll
        for (int ks = 0; ks < 4; ks++) {
            afr[ks][0] = *(const uint32_t*)(Abase + ks * 32);
            afr[ks][1] = *(const uint32_t*)(Abase + ks * 32 + 8 * ASTR * 2);
            afr[ks][2] = *(const uint32_t*)(Abase + ks * 32 + 16);
            afr[ks][3] = *(const uint32_t*)(Abase + ks * 32 + 8 * ASTR * 2 + 16);
        }
    }

    float acc[18][4];
    #pragma unroll
    for (int t = 0; t < 18; t++)
        #pragma unroll
        for (int q = 0; q < 4; q++) acc[t][q] = 0.f;

    {
        const char* Bbase = smem + OFF_B + g * (BSTR * 2) + 4 * tg;
        #pragma unroll
        for (int t = 0; t < 18; t++) {
            const char* Bt = Bbase + t * 8 * (BSTR * 2);
            #pragma unroll
            for (int ks = 0; ks < 4; ks++) {
                const uint32_t b0 = *(const uint32_t*)(Bt + ks * 32);
                const uint32_t b1 = *(const uint32_t*)(Bt + ks * 32 + 16);
                mma16816(acc[t], afr[ks], b0, b1);
            }
        }
    }
    __syncthreads();   // all mma reads of A/B done before stage aliases them

    // ---- Phase 5: scatter C frags into stage[b][vloc*9+d] (output order) ----
    float* stage = (float*)(smem + OFF_STAGE);
    {
        const int r0 = wid * 16 + g;
        #pragma unroll
        for (int t = 0; t < 18; t++) {
            const int col0 = t * 8 + 2 * tg;
            const int b0i = col0 / DIM, d0 = col0 - b0i * DIM;
            const int col1 = col0 + 1;
            const int b1i = col1 / DIM, d1 = col1 - b1i * DIM;
            stage[b0i * NELEM + r0 * DIM + d0]       = acc[t][0];
            stage[b1i * NELEM + r0 * DIM + d1]       = acc[t][1];
            stage[b0i * NELEM + (r0 + 8) * DIM + d0] = acc[t][2];
            stage[b1i * NELEM + (r0 + 8) * DIM + d1] = acc[t][3];
        }
    }
    __syncthreads();

    // ---- Phase 6: coalesced copy-out (stage[b][*] contiguous in out[b]) ----
    const int nvalid4 = (min(NELEM, (VNUM - v0) * DIM)) >> 2;
    const float4* st4 = (const float4*)stage;
    #pragma unroll
    for (int it = 0; it < (BATCH * NELEM / 4) / THREADS; it++) {     // 18
        const int f  = tid + it * THREADS;
        const int b  = f / (NELEM / 4);
        const int e4 = f - b * (NELEM / 4);
        if (e4 < nvalid4)
            *(float4*)(out + (size_t)b * ((size_t)VNUM * DIM) + (size_t)v0 * DIM + e4 * 4) =
                st4[f];
    }
}

extern "C" void kernel_launch(void* const* d_in, const int* in_sizes, int n_in,
                              void* d_out, int out_size) {
    const float* base_fs = (const float*)d_in[0];   // [16, 576] f32
    const float* ws      = (const float*)d_in[1];   // [800000] f32
    const void*  vb      = d_in[2];                 // [800000] i64 or i32 (detected)
    // d_in[3] = vv_index: statically repeat(arange(VNUM), 8); unused.
    float* out = (float*)d_out;                     // [16, 100000, 9] f32

    static bool attr_set = false;
    if (!attr_set) {
        cudaFuncSetAttribute(skin_mma_kernel,
                             cudaFuncAttributeMaxDynamicSharedMemorySize, SMEM_TOTAL);
        attr_set = true;
    }

    detect_vb_dtype_kernel<<<1, 256>>>((const int*)vb);
    const int blocks = (VNUM + TV - 1) / TV;        // 782
    skin_mma_kernel<<<blocks, THREADS, SMEM_TOTAL>>>(base_fs, ws, vb, out);
}